// round 16
// baseline (speedup 1.0000x reference)
#include <cuda_runtime.h>
#include <cuda_bf16.h>
#include <math.h>
#include <stdint.h>

// Problem constants
#define B_   64
#define E_   1280
#define H_   20
#define D_   64
#define NB_  7
#define BS_  64
#define L_   (NB_*BS_)      // 448
#define SCALING 0.125f      // 64^-0.5

// Scratch (device globals: allocation-free). 16B-aligned for float4 access.
__device__ __align__(16) float g_q[B_ * E_];
__device__ __align__(16) float g_k[B_ * E_];
__device__ __align__(16) float g_v[B_ * E_];
__device__ __align__(16) float g_attn[B_ * E_];

// PDL primitives (sm_90+)
__device__ __forceinline__ void pdl_trigger() {
    asm volatile("griddepcontrol.launch_dependents;");
}
__device__ __forceinline__ void pdl_wait() {
    asm volatile("griddepcontrol.wait;" ::: "memory");
}
__device__ __forceinline__ void l2_prefetch(const void* p) {
    asm volatile("prefetch.global.L2 [%0];" :: "l"(p));
}

// ---------------------------------------------------------------------------
// Init: biases into q/k/v accumulators and bo into d_out
// ---------------------------------------------------------------------------
__global__ void init_kernel(const float* __restrict__ bq, const float* __restrict__ bk,
                            const float* __restrict__ bv, const float* __restrict__ bo,
                            float* __restrict__ out) {
    pdl_trigger();                       // let qkv launch + run its mainloop now
    int i = blockIdx.x * blockDim.x + threadIdx.x;
    if (i < B_ * E_) {
        int j = i % E_;
        g_q[i] = bq[j];
        g_k[i] = bk[j];
        g_v[i] = bv[j];
        out[i] = bo[j];
    }
}

// ---------------------------------------------------------------------------
// bf16 mma.sync m16n8k16 (row.col), fp32 accumulate
// ---------------------------------------------------------------------------
__device__ __forceinline__ void mma_bf16(float* c,
                                         uint32_t a0, uint32_t a1, uint32_t a2, uint32_t a3,
                                         uint32_t b0, uint32_t b1) {
    asm volatile(
        "mma.sync.aligned.m16n8k16.row.col.f32.bf16.bf16.f32 "
        "{%0,%1,%2,%3}, {%4,%5,%6,%7}, {%8,%9}, {%0,%1,%2,%3};"
        : "+f"(c[0]), "+f"(c[1]), "+f"(c[2]), "+f"(c[3])
        : "r"(a0), "r"(a1), "r"(a2), "r"(a3), "r"(b0), "r"(b1));
}

// Vectorized global atomic add of a float2 (sm_90+).
__device__ __forceinline__ void red_add_v2(float* ptr, float x, float y) {
    asm volatile("red.global.add.v2.f32 [%0], {%1, %2};"
                 :: "l"(ptr), "f"(x), "f"(y) : "memory");
}

// Split float4 into packed-bf16x2 hi/lo planes.
__device__ __forceinline__ void splitpack(float4 v, uint32_t& h0, uint32_t& h1,
                                          uint32_t& l0, uint32_t& l1) {
    uint32_t bx = __float_as_uint(v.x), by = __float_as_uint(v.y);
    uint32_t bz = __float_as_uint(v.z), bw = __float_as_uint(v.w);
    uint32_t hx = bx & 0xFFFF0000u, hy = by & 0xFFFF0000u;
    uint32_t hz = bz & 0xFFFF0000u, hw = bw & 0xFFFF0000u;
    h0 = (bx >> 16) | hy;
    h1 = (bz >> 16) | hw;
    float rx = v.x - __uint_as_float(hx);
    float ry = v.y - __uint_as_float(hy);
    float rz = v.z - __uint_as_float(hz);
    float rw = v.w - __uint_as_float(hw);
    __nv_bfloat162 p0 = __floats2bfloat162_rn(rx, ry);
    __nv_bfloat162 p1 = __floats2bfloat162_rn(rz, rw);
    l0 = *(uint32_t*)&p0;
    l1 = *(uint32_t*)&p1;
}

// ---------------------------------------------------------------------------
// Tensor-core GEMM core (R10-proven: bf16 3-term, double-buffered smem).
// C[64, Ntile=128] += A[64,K] * W[N,K]^T over [k0,k0+KC)
// 256 threads = 8 warps: 2 m-warps (m32) x 4 n-warps (n32).
// pdl_wait() before the epilogue: mainloop overlaps the predecessor kernel.
// ---------------------------------------------------------------------------
#define GTN 128
#define GTK 32
#define PLW 20
#define APW (64 * PLW)
#define WPW (128 * PLW)
#define BUFW (2 * APW + 2 * WPW)
#define SMEM_WORDS (2 * BUFW)     // 61440 B

__device__ __forceinline__ void gemm_core(const float* __restrict__ A,
                                          const float* __restrict__ W,
                                          float* __restrict__ out,
                                          int j0, int k0, int KC) {
    extern __shared__ __align__(16) uint32_t smem[];
    const int t    = threadIdx.x;
    const int warp = t >> 5;
    const int lane = t & 31;
    const int lg   = lane >> 2;
    const int lt   = lane & 3;
    const int am   = (warp & 1) * 32;
    const int bn   = (warp >> 1) * 32;

    float c[2][4][4] = {};
    float4 ra[2], rw[4];

    const int lrowA = t >> 3;
    const int lq    = t & 7;

    auto load_tile = [&](int kt) {
        #pragma unroll
        for (int r = 0; r < 2; r++)
            ra[r] = *(const float4*)(A + (lrowA + r * 32) * E_ + kt + lq * 4);
        #pragma unroll
        for (int r = 0; r < 4; r++)
            rw[r] = *(const float4*)(W + (size_t)(j0 + lrowA + r * 32) * E_ + kt + lq * 4);
    };
    auto store_tile = [&](int buf) {
        uint32_t* Ah = smem + buf * BUFW;
        uint32_t* Al = Ah + APW;
        uint32_t* Wh = Al + APW;
        uint32_t* Wl = Wh + WPW;
        #pragma unroll
        for (int r = 0; r < 2; r++) {
            uint32_t h0, h1, l0, l1;
            splitpack(ra[r], h0, h1, l0, l1);
            int base = (lrowA + r * 32) * PLW + lq * 2;
            Ah[base] = h0; Ah[base + 1] = h1;
            Al[base] = l0; Al[base + 1] = l1;
        }
        #pragma unroll
        for (int r = 0; r < 4; r++) {
            uint32_t h0, h1, l0, l1;
            splitpack(rw[r], h0, h1, l0, l1);
            int base = (lrowA + r * 32) * PLW + lq * 2;
            Wh[base] = h0; Wh[base + 1] = h1;
            Wl[base] = l0; Wl[base + 1] = l1;
        }
    };
    auto mma_tiles = [&](int buf) {
        uint32_t* Ah = smem + buf * BUFW;
        uint32_t* Al = Ah + APW;
        uint32_t* Wh = Al + APW;
        uint32_t* Wl = Wh + WPW;
        #pragma unroll
        for (int ks = 0; ks < GTK / 16; ks++) {
            int kw = ks * 8;
            uint32_t ah[2][4], al[2][4];
            #pragma unroll
            for (int mi = 0; mi < 2; mi++) {
                int r0 = (am + mi * 16 + lg) * PLW + kw + lt;
                int r1 = r0 + 8 * PLW;
                ah[mi][0] = Ah[r0];     ah[mi][1] = Ah[r1];
                ah[mi][2] = Ah[r0 + 4]; ah[mi][3] = Ah[r1 + 4];
                al[mi][0] = Al[r0];     al[mi][1] = Al[r1];
                al[mi][2] = Al[r0 + 4]; al[mi][3] = Al[r1 + 4];
            }
            #pragma unroll
            for (int nt = 0; nt < 4; nt++) {
                int rb = (bn + nt * 8 + lg) * PLW + kw + lt;
                uint32_t bh0 = Wh[rb], bh1 = Wh[rb + 4];
                uint32_t bl0 = Wl[rb], bl1 = Wl[rb + 4];
                #pragma unroll
                for (int mi = 0; mi < 2; mi++) {
                    mma_bf16(c[mi][nt], ah[mi][0], ah[mi][1], ah[mi][2], ah[mi][3], bh0, bh1);
                    mma_bf16(c[mi][nt], ah[mi][0], ah[mi][1], ah[mi][2], ah[mi][3], bl0, bl1);
                    mma_bf16(c[mi][nt], al[mi][0], al[mi][1], al[mi][2], al[mi][3], bh0, bh1);
                }
            }
        }
    };

    const int ntiles = KC / GTK;
    load_tile(k0);
    store_tile(0);
    __syncthreads();
    for (int it = 0; it < ntiles; it++) {
        if (it + 1 < ntiles) load_tile(k0 + (it + 1) * GTK);
        mma_tiles(it & 1);
        if (it + 1 < ntiles) {
            store_tile((it + 1) & 1);
            __syncthreads();
        }
    }

    // Predecessor (init for qkv) must be complete before red-add into its output.
    pdl_wait();

    #pragma unroll
    for (int mi = 0; mi < 2; mi++) {
        int row0 = am + mi * 16 + lg;
        #pragma unroll
        for (int nt = 0; nt < 4; nt++) {
            int col = j0 + bn + nt * 8 + 2 * lt;
            red_add_v2(&out[ row0      * E_ + col], c[mi][nt][0], c[mi][nt][1]);
            red_add_v2(&out[(row0 + 8) * E_ + col], c[mi][nt][2], c[mi][nt][3]);
        }
    }
}

// QKV fused: grid (10 n-tiles, 10 k-splits, 3 weights), KC=128 -> 300 blocks
__global__ void __launch_bounds__(256) qkv_kernel(const float* __restrict__ hidden,
                                                  const float* __restrict__ wq,
                                                  const float* __restrict__ wk,
                                                  const float* __restrict__ wv) {
    pdl_trigger();                       // let attn launch + prefetch K into L2
    const float* W;
    float* out;
    if (blockIdx.z == 0)      { W = wq; out = g_q; }
    else if (blockIdx.z == 1) { W = wk; out = g_k; }
    else                      { W = wv; out = g_v; }
    gemm_core(hidden, W, out, blockIdx.x * GTN, blockIdx.y * 128, 128);
}

// O-proj: grid (10 n-tiles, 20 k-splits), KC=64 -> 200 blocks
__global__ void __launch_bounds__(256) oproj_kernel(const float* __restrict__ wo,
                                                    float* __restrict__ out) {
    // Prefetch this CTA's FULL W working set (128 rows x 64 k = 32 KB) into L2
    // while attn is still running. 256 lines, 1 per thread per k-tile.
    {
        const int t   = threadIdx.x;
        const int j0  = blockIdx.x * GTN;
        const int k0  = blockIdx.y * 64;
        const int row = t >> 1;          // 0..127
        const int kq  = t & 1;           // 0/1 (two 128B lines per 64-float row)
        l2_prefetch(wo + (size_t)(j0 + row) * E_ + k0 + kq * 32);
    }
    pdl_wait();                          // g_attn (and transitively d_out init) ready
    gemm_core(g_attn, wo, out, blockIdx.x * GTN, blockIdx.y * 64, 64);
}

// ---------------------------------------------------------------------------
// Attention: one CTA per (b, h). 256 threads. (R10 configuration + K prefetch)
// ---------------------------------------------------------------------------
__global__ void attn_kernel(const float* __restrict__ kcache,
                            const float* __restrict__ vcache,
                            const int* __restrict__ cache_position,
                            const int* __restrict__ block_tables) {
    __shared__ __align__(16) float qs[D_];
    __shared__ __align__(16) float sc[L_];
    __shared__ __align__(16) float pvb[16][D_];
    __shared__ float redbuf[8];
    __shared__ float red2[8];
    __shared__ int   bts[NB_];

    pdl_trigger();                       // let oproj launch + prefetch W

    const int b = blockIdx.x;
    const int h = blockIdx.y;
    const int tid  = threadIdx.x;
    const int warp = tid >> 5;
    const int lane = tid & 31;

    // Prologue independent of qkv output:
    if (tid < NB_) bts[tid] = block_tables[b * NB_ + tid];
    const int pos = cache_position[b];
    const int n   = pos + 1;

    const size_t bh_base = ((size_t)b * H_ + h) * NB_;

    // Prefetch this CTA's entire K working set into L2 while qkv still runs.
    // (addresses depend only on block_tables/cache_position, not on qkv output)
    for (int l = tid; l < n; l += 256) {
        int blk = block_tables[b * NB_ + (l >> 6)];
        const float* kr = kcache + ((bh_base + blk) * BS_ + (l & 63)) * D_;
        l2_prefetch(kr);
        l2_prefetch(kr + 32);            // second 128B line of the 256B row
    }

    pdl_wait();                          // qkv complete: g_q/g_k/g_v valid

    if (tid < D_)  qs[tid]  = g_q[b * E_ + h * D_ + tid];
    __syncthreads();

    const float* knew = &g_k[b * E_ + h * D_];
    const float* vnew = &g_v[b * E_ + h * D_];

    // ---- scores: 2 rows per warp (16 lanes each), float4 loads ----
    const int half = lane >> 4;
    const int hl   = lane & 15;
    for (int l0 = warp * 2; l0 < n; l0 += 16) {
        int l = l0 + half;
        float p = 0.f;
        if (l < n) {
            const float* kr;
            if (l == pos) {
                kr = knew;
            } else {
                int blk = bts[l >> 6];
                kr = kcache + ((bh_base + blk) * BS_ + (l & 63)) * D_;
            }
            float4 kv = ((const float4*)kr)[hl];
            float4 qv = ((const float4*)qs)[hl];
            p = qv.x * kv.x + qv.y * kv.y + qv.z * kv.z + qv.w * kv.w;
        }
        #pragma unroll
        for (int o = 8; o > 0; o >>= 1)
            p += __shfl_xor_sync(0xFFFFFFFFu, p, o);
        if (hl == 0 && l < n) sc[l] = p * SCALING;
    }
    __syncthreads();

    // ---- softmax: max ----
    float m = -1e30f;
    for (int l = tid; l < n; l += 256) m = fmaxf(m, sc[l]);
    #pragma unroll
    for (int o = 16; o > 0; o >>= 1)
        m = fmaxf(m, __shfl_xor_sync(0xFFFFFFFFu, m, o));
    if (lane == 0) redbuf[warp] = m;
    __syncthreads();
    if (warp == 0) {
        float x = (lane < 8) ? redbuf[lane] : -1e30f;
        #pragma unroll
        for (int o = 4; o > 0; o >>= 1)
            x = fmaxf(x, __shfl_xor_sync(0xFFFFFFFFu, x, o));
        if (lane == 0) redbuf[0] = x;
    }
    __syncthreads();
    m = redbuf[0];

    // ---- exp + sum ----
    float s = 0.f;
    for (int l = tid; l < n; l += 256) {
        float e = __expf(sc[l] - m);
        sc[l] = e;
        s += e;
    }
    #pragma unroll
    for (int o = 16; o > 0; o >>= 1)
        s += __shfl_xor_sync(0xFFFFFFFFu, s, o);
    if (lane == 0) red2[warp] = s;
    __syncthreads();
    if (warp == 0) {
        float x = (lane < 8) ? red2[lane] : 0.f;
        #pragma unroll
        for (int o = 4; o > 0; o >>= 1)
            x += __shfl_xor_sync(0xFFFFFFFFu, x, o);
        if (lane == 0) red2[0] = x;
    }
    __syncthreads();
    const float inv = 1.0f / red2[0];

    // ---- P * V: 16 l-partitions x 16 d-quads, float4 loads ----
    const int dq   = tid & 15;
    const int part = tid >> 4;
    float4 acc = make_float4(0.f, 0.f, 0.f, 0.f);
    #pragma unroll 4
    for (int l = part; l < n; l += 16) {
        const float* vr;
        if (l == pos) {
            vr = vnew;
        } else {
            int blk = bts[l >> 6];
            vr = vcache + ((bh_base + blk) * BS_ + (l & 63)) * D_;
        }
        float4 v = ((const float4*)vr)[dq];
        float p = sc[l];
        acc.x += p * v.x; acc.y += p * v.y; acc.z += p * v.z; acc.w += p * v.w;
    }
    *(float4*)&pvb[part][dq * 4] = acc;
    __syncthreads();
    if (tid < D_) {
        float s2 = 0.f;
        #pragma unroll
        for (int p = 0; p < 16; p++) s2 += pvb[p][tid];
        g_attn[b * E_ + h * D_ + tid] = s2 * inv;
    }
}

// ---------------------------------------------------------------------------
extern "C" void kernel_launch(void* const* d_in, const int* in_sizes, int n_in,
                              void* d_out, int out_size) {
    const float* hidden = (const float*)d_in[0];
    const float* kcache = (const float*)d_in[1];
    const float* vcache = (const float*)d_in[2];
    const float* wq     = (const float*)d_in[3];
    const float* bq     = (const float*)d_in[4];
    const float* wk     = (const float*)d_in[5];
    const float* bk     = (const float*)d_in[6];
    const float* wv     = (const float*)d_in[7];
    const float* bv     = (const float*)d_in[8];
    const float* wo     = (const float*)d_in[9];
    const float* bo     = (const float*)d_in[10];
    const int*   cpos   = (const int*)d_in[11];
    const int*   btab   = (const int*)d_in[12];
    float* out = (float*)d_out;

    const int smem_bytes = SMEM_WORDS * 4;   // 61440
    cudaFuncSetAttribute(qkv_kernel,   cudaFuncAttributeMaxDynamicSharedMemorySize, smem_bytes);
    cudaFuncSetAttribute(oproj_kernel, cudaFuncAttributeMaxDynamicSharedMemorySize, smem_bytes);

    // PDL attribute for the secondary launches
    cudaLaunchAttribute pdl_attr[1];
    pdl_attr[0].id = cudaLaunchAttributeProgrammaticStreamSerialization;
    pdl_attr[0].val.programmaticStreamSerializationAllowed = 1;

    init_kernel<<<(B_ * E_ + 255) / 256, 256>>>(bq, bk, bv, bo, out);

    {   // QKV fused (PDL secondary): 10 x 10 x 3 = 300 blocks
        cudaLaunchConfig_t cfg = {};
        cfg.gridDim = dim3(E_ / GTN, 10, 3);
        cfg.blockDim = dim3(256, 1, 1);
        cfg.dynamicSmemBytes = smem_bytes;
        cfg.stream = 0;
        cfg.attrs = pdl_attr;
        cfg.numAttrs = 1;
        cudaLaunchKernelEx(&cfg, qkv_kernel, hidden, wq, wk, wv);
    }
    {   // Attention (PDL secondary): (B, H)
        cudaLaunchConfig_t cfg = {};
        cfg.gridDim = dim3(B_, H_, 1);
        cfg.blockDim = dim3(256, 1, 1);
        cfg.dynamicSmemBytes = 0;
        cfg.stream = 0;
        cfg.attrs = pdl_attr;
        cfg.numAttrs = 1;
        cudaLaunchKernelEx(&cfg, attn_kernel, kcache, vcache, cpos, btab);
    }
    {   // O-proj (PDL secondary): 10 x 20 = 200 blocks
        cudaLaunchConfig_t cfg = {};
        cfg.gridDim = dim3(E_ / GTN, 20, 1);
        cfg.blockDim = dim3(256, 1, 1);
        cfg.dynamicSmemBytes = smem_bytes;
        cfg.stream = 0;
        cfg.attrs = pdl_attr;
        cfg.numAttrs = 1;
        cudaLaunchKernelEx(&cfg, oproj_kernel, wo, out);
    }
}

// round 17
// speedup vs baseline: 1.1073x; 1.1073x over previous
#include <cuda_runtime.h>
#include <cuda_bf16.h>
#include <math.h>
#include <stdint.h>

// Problem constants
#define B_   64
#define E_   1280
#define H_   20
#define D_   64
#define NB_  7
#define BS_  64
#define L_   (NB_*BS_)      // 448
#define SCALING 0.125f      // 64^-0.5

// Scratch (device globals: allocation-free). 16B-aligned for float4 access.
__device__ __align__(16) float g_q[B_ * E_];
__device__ __align__(16) float g_k[B_ * E_];
__device__ __align__(16) float g_v[B_ * E_];
__device__ __align__(16) float g_attn[B_ * E_];
__device__ int g_head_done[H_];     // per-head attn completion count (reset by qkv)

// PDL primitives (sm_90+)
__device__ __forceinline__ void pdl_trigger() {
    asm volatile("griddepcontrol.launch_dependents;");
}
__device__ __forceinline__ void pdl_wait() {
    asm volatile("griddepcontrol.wait;" ::: "memory");
}
__device__ __forceinline__ void l2_prefetch(const void* p) {
    asm volatile("prefetch.global.L2 [%0];" :: "l"(p));
}

// ---------------------------------------------------------------------------
// Init: biases into q/k/v accumulators and bo into d_out
// ---------------------------------------------------------------------------
__global__ void init_kernel(const float* __restrict__ bq, const float* __restrict__ bk,
                            const float* __restrict__ bv, const float* __restrict__ bo,
                            float* __restrict__ out) {
    pdl_trigger();                       // let qkv launch + run its mainloop now
    int i = blockIdx.x * blockDim.x + threadIdx.x;
    if (i < B_ * E_) {
        int j = i % E_;
        g_q[i] = bq[j];
        g_k[i] = bk[j];
        g_v[i] = bv[j];
        out[i] = bo[j];
    }
}

// ---------------------------------------------------------------------------
// bf16 mma.sync m16n8k16 (row.col), fp32 accumulate
// ---------------------------------------------------------------------------
__device__ __forceinline__ void mma_bf16(float* c,
                                         uint32_t a0, uint32_t a1, uint32_t a2, uint32_t a3,
                                         uint32_t b0, uint32_t b1) {
    asm volatile(
        "mma.sync.aligned.m16n8k16.row.col.f32.bf16.bf16.f32 "
        "{%0,%1,%2,%3}, {%4,%5,%6,%7}, {%8,%9}, {%0,%1,%2,%3};"
        : "+f"(c[0]), "+f"(c[1]), "+f"(c[2]), "+f"(c[3])
        : "r"(a0), "r"(a1), "r"(a2), "r"(a3), "r"(b0), "r"(b1));
}

// Vectorized global atomic add of a float2 (sm_90+).
__device__ __forceinline__ void red_add_v2(float* ptr, float x, float y) {
    asm volatile("red.global.add.v2.f32 [%0], {%1, %2};"
                 :: "l"(ptr), "f"(x), "f"(y) : "memory");
}

// Split float4 into packed-bf16x2 hi/lo planes.
__device__ __forceinline__ void splitpack(float4 v, uint32_t& h0, uint32_t& h1,
                                          uint32_t& l0, uint32_t& l1) {
    uint32_t bx = __float_as_uint(v.x), by = __float_as_uint(v.y);
    uint32_t bz = __float_as_uint(v.z), bw = __float_as_uint(v.w);
    uint32_t hx = bx & 0xFFFF0000u, hy = by & 0xFFFF0000u;
    uint32_t hz = bz & 0xFFFF0000u, hw = bw & 0xFFFF0000u;
    h0 = (bx >> 16) | hy;
    h1 = (bz >> 16) | hw;
    float rx = v.x - __uint_as_float(hx);
    float ry = v.y - __uint_as_float(hy);
    float rz = v.z - __uint_as_float(hz);
    float rw = v.w - __uint_as_float(hw);
    __nv_bfloat162 p0 = __floats2bfloat162_rn(rx, ry);
    __nv_bfloat162 p1 = __floats2bfloat162_rn(rz, rw);
    l0 = *(uint32_t*)&p0;
    l1 = *(uint32_t*)&p1;
}

// ---------------------------------------------------------------------------
// Tensor-core GEMM core (R10-proven: bf16 3-term, double-buffered smem).
// C[64, Ntile=128] += A[64,K] * W[N,K]^T over [k0,k0+KC)
// do_wait: issue pdl_wait() before the epilogue (qkv needs init complete;
// oproj's ordering is provided by the per-head spin instead).
// ---------------------------------------------------------------------------
#define GTN 128
#define GTK 32
#define PLW 20
#define APW (64 * PLW)
#define WPW (128 * PLW)
#define BUFW (2 * APW + 2 * WPW)
#define SMEM_WORDS (2 * BUFW)     // 61440 B

__device__ __forceinline__ void gemm_core(const float* __restrict__ A,
                                          const float* __restrict__ W,
                                          float* __restrict__ out,
                                          int j0, int k0, int KC, bool do_wait) {
    extern __shared__ __align__(16) uint32_t smem[];
    const int t    = threadIdx.x;
    const int warp = t >> 5;
    const int lane = t & 31;
    const int lg   = lane >> 2;
    const int lt   = lane & 3;
    const int am   = (warp & 1) * 32;
    const int bn   = (warp >> 1) * 32;

    float c[2][4][4] = {};
    float4 ra[2], rw[4];

    const int lrowA = t >> 3;
    const int lq    = t & 7;

    auto load_tile = [&](int kt) {
        #pragma unroll
        for (int r = 0; r < 2; r++)
            ra[r] = *(const float4*)(A + (lrowA + r * 32) * E_ + kt + lq * 4);
        #pragma unroll
        for (int r = 0; r < 4; r++)
            rw[r] = *(const float4*)(W + (size_t)(j0 + lrowA + r * 32) * E_ + kt + lq * 4);
    };
    auto store_tile = [&](int buf) {
        uint32_t* Ah = smem + buf * BUFW;
        uint32_t* Al = Ah + APW;
        uint32_t* Wh = Al + APW;
        uint32_t* Wl = Wh + WPW;
        #pragma unroll
        for (int r = 0; r < 2; r++) {
            uint32_t h0, h1, l0, l1;
            splitpack(ra[r], h0, h1, l0, l1);
            int base = (lrowA + r * 32) * PLW + lq * 2;
            Ah[base] = h0; Ah[base + 1] = h1;
            Al[base] = l0; Al[base + 1] = l1;
        }
        #pragma unroll
        for (int r = 0; r < 4; r++) {
            uint32_t h0, h1, l0, l1;
            splitpack(rw[r], h0, h1, l0, l1);
            int base = (lrowA + r * 32) * PLW + lq * 2;
            Wh[base] = h0; Wh[base + 1] = h1;
            Wl[base] = l0; Wl[base + 1] = l1;
        }
    };
    auto mma_tiles = [&](int buf) {
        uint32_t* Ah = smem + buf * BUFW;
        uint32_t* Al = Ah + APW;
        uint32_t* Wh = Al + APW;
        uint32_t* Wl = Wh + WPW;
        #pragma unroll
        for (int ks = 0; ks < GTK / 16; ks++) {
            int kw = ks * 8;
            uint32_t ah[2][4], al[2][4];
            #pragma unroll
            for (int mi = 0; mi < 2; mi++) {
                int r0 = (am + mi * 16 + lg) * PLW + kw + lt;
                int r1 = r0 + 8 * PLW;
                ah[mi][0] = Ah[r0];     ah[mi][1] = Ah[r1];
                ah[mi][2] = Ah[r0 + 4]; ah[mi][3] = Ah[r1 + 4];
                al[mi][0] = Al[r0];     al[mi][1] = Al[r1];
                al[mi][2] = Al[r0 + 4]; al[mi][3] = Al[r1 + 4];
            }
            #pragma unroll
            for (int nt = 0; nt < 4; nt++) {
                int rb = (bn + nt * 8 + lg) * PLW + kw + lt;
                uint32_t bh0 = Wh[rb], bh1 = Wh[rb + 4];
                uint32_t bl0 = Wl[rb], bl1 = Wl[rb + 4];
                #pragma unroll
                for (int mi = 0; mi < 2; mi++) {
                    mma_bf16(c[mi][nt], ah[mi][0], ah[mi][1], ah[mi][2], ah[mi][3], bh0, bh1);
                    mma_bf16(c[mi][nt], ah[mi][0], ah[mi][1], ah[mi][2], ah[mi][3], bl0, bl1);
                    mma_bf16(c[mi][nt], al[mi][0], al[mi][1], al[mi][2], al[mi][3], bh0, bh1);
                }
            }
        }
    };

    const int ntiles = KC / GTK;
    load_tile(k0);
    store_tile(0);
    __syncthreads();
    for (int it = 0; it < ntiles; it++) {
        if (it + 1 < ntiles) load_tile(k0 + (it + 1) * GTK);
        mma_tiles(it & 1);
        if (it + 1 < ntiles) {
            store_tile((it + 1) & 1);
            __syncthreads();
        }
    }

    if (do_wait) pdl_wait();   // qkv: init must complete before red-add into its output

    #pragma unroll
    for (int mi = 0; mi < 2; mi++) {
        int row0 = am + mi * 16 + lg;
        #pragma unroll
        for (int nt = 0; nt < 4; nt++) {
            int col = j0 + bn + nt * 8 + 2 * lt;
            red_add_v2(&out[ row0      * E_ + col], c[mi][nt][0], c[mi][nt][1]);
            red_add_v2(&out[(row0 + 8) * E_ + col], c[mi][nt][2], c[mi][nt][3]);
        }
    }
}

// QKV fused: grid (10 n-tiles, 10 k-splits, 3 weights), KC=128 -> 300 blocks
__global__ void __launch_bounds__(256) qkv_kernel(const float* __restrict__ hidden,
                                                  const float* __restrict__ wq,
                                                  const float* __restrict__ wk,
                                                  const float* __restrict__ wv) {
    // Reset per-head counters BEFORE triggering dependents: PDL guarantees attn
    // (and transitively oproj) launch only after ALL qkv CTAs pass the trigger,
    // so no dependent can observe a stale counter from a previous graph replay.
    if ((blockIdx.x | blockIdx.y | blockIdx.z) == 0 && threadIdx.x < H_)
        atomicExch(&g_head_done[threadIdx.x], 0);
    __threadfence();
    pdl_trigger();

    const float* W;
    float* out;
    if (blockIdx.z == 0)      { W = wq; out = g_q; }
    else if (blockIdx.z == 1) { W = wk; out = g_k; }
    else                      { W = wv; out = g_v; }
    gemm_core(hidden, W, out, blockIdx.x * GTN, blockIdx.y * 128, 128, true);
}

// O-proj: grid (10 n-tiles, 20 k-splits=heads), KC=64 -> 200 blocks.
// k-split s reads g_attn columns [s*64, s*64+64) == head s only: spin on the
// per-head counter instead of waiting for the whole attn grid.
__global__ void __launch_bounds__(256) oproj_kernel(const float* __restrict__ wo,
                                                    float* __restrict__ out) {
    // Prefetch this CTA's first W tile into L2 while attn is still running.
    {
        const int t = threadIdx.x;
        const int lrow = t >> 3;
        const int lq   = t & 7;
        const int j0   = blockIdx.x * GTN;
        const int k0   = blockIdx.y * 64;
        #pragma unroll
        for (int r = 0; r < 4; r++)
            l2_prefetch(wo + (size_t)(j0 + lrow + r * 32) * E_ + k0 + lq * 4);
    }
    // Wait for head blockIdx.y of attention to complete (all 64 batches).
    if (threadIdx.x == 0) {
        while (atomicAdd(&g_head_done[blockIdx.y], 0) < B_)
            __nanosleep(64);
        __threadfence();
    }
    __syncthreads();
    gemm_core(g_attn, wo, out, blockIdx.x * GTN, blockIdx.y * 64, 64, false);
}

// ---------------------------------------------------------------------------
// Attention: one CTA per (b, h). 256 threads. (R15 configuration + head counter)
// ---------------------------------------------------------------------------
__global__ void attn_kernel(const float* __restrict__ kcache,
                            const float* __restrict__ vcache,
                            const int* __restrict__ cache_position,
                            const int* __restrict__ block_tables) {
    __shared__ __align__(16) float qs[D_];
    __shared__ __align__(16) float sc[L_];
    __shared__ __align__(16) float pvb[16][D_];
    __shared__ float redbuf[8];
    __shared__ float red2[8];
    __shared__ int   bts[NB_];

    pdl_trigger();                       // let oproj launch + prefetch W

    const int b = blockIdx.x;
    const int h = blockIdx.y;
    const int tid  = threadIdx.x;
    const int warp = tid >> 5;
    const int lane = tid & 31;

    // Prologue independent of qkv output:
    if (tid < NB_) bts[tid] = block_tables[b * NB_ + tid];
    const int pos = cache_position[b];
    const int n   = pos + 1;

    pdl_wait();                          // qkv complete: g_q/g_k/g_v valid

    if (tid < D_)  qs[tid]  = g_q[b * E_ + h * D_ + tid];
    __syncthreads();

    const size_t bh_base = ((size_t)b * H_ + h) * NB_;
    const float* knew = &g_k[b * E_ + h * D_];
    const float* vnew = &g_v[b * E_ + h * D_];

    // ---- scores: 2 rows per warp (16 lanes each), float4 loads ----
    const int half = lane >> 4;
    const int hl   = lane & 15;
    for (int l0 = warp * 2; l0 < n; l0 += 16) {
        int l = l0 + half;
        float p = 0.f;
        if (l < n) {
            const float* kr;
            if (l == pos) {
                kr = knew;
            } else {
                int blk = bts[l >> 6];
                kr = kcache + ((bh_base + blk) * BS_ + (l & 63)) * D_;
            }
            float4 kv = ((const float4*)kr)[hl];
            float4 qv = ((const float4*)qs)[hl];
            p = qv.x * kv.x + qv.y * kv.y + qv.z * kv.z + qv.w * kv.w;
        }
        #pragma unroll
        for (int o = 8; o > 0; o >>= 1)
            p += __shfl_xor_sync(0xFFFFFFFFu, p, o);
        if (hl == 0 && l < n) sc[l] = p * SCALING;
    }
    __syncthreads();

    // ---- softmax: max ----
    float m = -1e30f;
    for (int l = tid; l < n; l += 256) m = fmaxf(m, sc[l]);
    #pragma unroll
    for (int o = 16; o > 0; o >>= 1)
        m = fmaxf(m, __shfl_xor_sync(0xFFFFFFFFu, m, o));
    if (lane == 0) redbuf[warp] = m;
    __syncthreads();
    if (warp == 0) {
        float x = (lane < 8) ? redbuf[lane] : -1e30f;
        #pragma unroll
        for (int o = 4; o > 0; o >>= 1)
            x = fmaxf(x, __shfl_xor_sync(0xFFFFFFFFu, x, o));
        if (lane == 0) redbuf[0] = x;
    }
    __syncthreads();
    m = redbuf[0];

    // ---- exp + sum ----
    float s = 0.f;
    for (int l = tid; l < n; l += 256) {
        float e = __expf(sc[l] - m);
        sc[l] = e;
        s += e;
    }
    #pragma unroll
    for (int o = 16; o > 0; o >>= 1)
        s += __shfl_xor_sync(0xFFFFFFFFu, s, o);
    if (lane == 0) red2[warp] = s;
    __syncthreads();
    if (warp == 0) {
        float x = (lane < 8) ? red2[lane] : 0.f;
        #pragma unroll
        for (int o = 4; o > 0; o >>= 1)
            x += __shfl_xor_sync(0xFFFFFFFFu, x, o);
        if (lane == 0) red2[0] = x;
    }
    __syncthreads();
    const float inv = 1.0f / red2[0];

    // ---- P * V: 16 l-partitions x 16 d-quads, float4 loads ----
    const int dq   = tid & 15;
    const int part = tid >> 4;
    float4 acc = make_float4(0.f, 0.f, 0.f, 0.f);
    #pragma unroll 4
    for (int l = part; l < n; l += 16) {
        const float* vr;
        if (l == pos) {
            vr = vnew;
        } else {
            int blk = bts[l >> 6];
            vr = vcache + ((bh_base + blk) * BS_ + (l & 63)) * D_;
        }
        float4 v = ((const float4*)vr)[dq];
        float p = sc[l];
        acc.x += p * v.x; acc.y += p * v.y; acc.z += p * v.z; acc.w += p * v.w;
    }
    *(float4*)&pvb[part][dq * 4] = acc;
    __syncthreads();
    if (tid < D_) {
        float s2 = 0.f;
        #pragma unroll
        for (int p = 0; p < 16; p++) s2 += pvb[p][tid];
        g_attn[b * E_ + h * D_ + tid] = s2 * inv;
    }

    // Signal head completion (g_attn writes made visible first).
    __threadfence();
    __syncthreads();
    if (tid == 0) atomicAdd(&g_head_done[h], 1);
}

// ---------------------------------------------------------------------------
extern "C" void kernel_launch(void* const* d_in, const int* in_sizes, int n_in,
                              void* d_out, int out_size) {
    const float* hidden = (const float*)d_in[0];
    const float* kcache = (const float*)d_in[1];
    const float* vcache = (const float*)d_in[2];
    const float* wq     = (const float*)d_in[3];
    const float* bq     = (const float*)d_in[4];
    const float* wk     = (const float*)d_in[5];
    const float* bk     = (const float*)d_in[6];
    const float* wv     = (const float*)d_in[7];
    const float* bv     = (const float*)d_in[8];
    const float* wo     = (const float*)d_in[9];
    const float* bo     = (const float*)d_in[10];
    const int*   cpos   = (const int*)d_in[11];
    const int*   btab   = (const int*)d_in[12];
    float* out = (float*)d_out;

    const int smem_bytes = SMEM_WORDS * 4;   // 61440
    cudaFuncSetAttribute(qkv_kernel,   cudaFuncAttributeMaxDynamicSharedMemorySize, smem_bytes);
    cudaFuncSetAttribute(oproj_kernel, cudaFuncAttributeMaxDynamicSharedMemorySize, smem_bytes);

    // PDL attribute for the secondary launches
    cudaLaunchAttribute pdl_attr[1];
    pdl_attr[0].id = cudaLaunchAttributeProgrammaticStreamSerialization;
    pdl_attr[0].val.programmaticStreamSerializationAllowed = 1;

    init_kernel<<<(B_ * E_ + 255) / 256, 256>>>(bq, bk, bv, bo, out);

    {   // QKV fused (PDL secondary): 10 x 10 x 3 = 300 blocks
        cudaLaunchConfig_t cfg = {};
        cfg.gridDim = dim3(E_ / GTN, 10, 3);
        cfg.blockDim = dim3(256, 1, 1);
        cfg.dynamicSmemBytes = smem_bytes;
        cfg.stream = 0;
        cfg.attrs = pdl_attr;
        cfg.numAttrs = 1;
        cudaLaunchKernelEx(&cfg, qkv_kernel, hidden, wq, wk, wv);
    }
    {   // Attention (PDL secondary): (B, H)
        cudaLaunchConfig_t cfg = {};
        cfg.gridDim = dim3(B_, H_, 1);
        cfg.blockDim = dim3(256, 1, 1);
        cfg.dynamicSmemBytes = 0;
        cfg.stream = 0;
        cfg.attrs = pdl_attr;
        cfg.numAttrs = 1;
        cudaLaunchKernelEx(&cfg, attn_kernel, kcache, vcache, cpos, btab);
    }
    {   // O-proj (PDL secondary): 10 x 20 = 200 blocks; per-head spin inside
        cudaLaunchConfig_t cfg = {};
        cfg.gridDim = dim3(E_ / GTN, 20, 1);
        cfg.blockDim = dim3(256, 1, 1);
        cfg.dynamicSmemBytes = smem_bytes;
        cfg.stream = 0;
        cfg.attrs = pdl_attr;
        cfg.numAttrs = 1;
        cudaLaunchKernelEx(&cfg, oproj_kernel, wo, out);
    }
}